// round 7
// baseline (speedup 1.0000x reference)
#include <cuda_runtime.h>
#include <cuda_bf16.h>
#include <cuda_fp8.h>
#include <stdint.h>

// ---------------------------------------------------------------------------
// InfoNCELoss on GB300 (sm_103 legacy mma.sync path, FP8 e4m3 m16n8k32)
// R7: no f32 copies (colsum from raw input x invnorm), 4-slot bulk ring,
//     log/div-free pos epilogue (first-order exact decomposition).
// ---------------------------------------------------------------------------

#define DDIM 512
#define FP8_SCALE 32.0f

// fp8 matrices, TILED layout: [panel(128r)][kt(8)][r(128)][64B], swizzled chunks
__device__ __align__(1024) uint32_t g_Anq[(size_t)4096  * 128];
__device__ __align__(1024) uint32_t g_Pnq[(size_t)4096  * 128];
__device__ __align__(1024) uint32_t g_Nnq[(size_t)16384 * 128];
__device__ float    g_invA[4096];
__device__ float    g_invP[4096];
__device__ float    g_invN[16384];
__device__ float    g_S[4096];
__device__ double   g_sum_loss;
__device__ double   g_cs[3][DDIM];

// ============================ PTX helpers ==================================
__device__ __forceinline__ uint32_t smem_to_u32(const void* p) {
    uint32_t a;
    asm("{ .reg .u64 t; cvta.to.shared.u64 t, %1; cvt.u32.u64 %0, t; }"
        : "=r"(a) : "l"(p));
    return a;
}
__device__ __forceinline__ void bulk_cp(uint32_t dst, const void* src,
                                        uint32_t bytes, uint32_t mbar) {
    asm volatile(
        "cp.async.bulk.shared::cta.global.mbarrier::complete_tx::bytes "
        "[%0], [%1], %2, [%3];"
        :: "r"(dst), "l"(src), "r"(bytes), "r"(mbar) : "memory");
}
#define MBARRIER_INIT(mbar, count) \
    asm volatile("mbarrier.init.shared.b64 [%0], %1;" \
        :: "r"((uint32_t)(mbar)), "r"((uint32_t)(count)) : "memory")
#define MBARRIER_EXPECT_TX(mbar, bytes) \
    asm volatile("mbarrier.arrive.expect_tx.shared.b64 _, [%0], %1;" \
        :: "r"((uint32_t)(mbar)), "r"((uint32_t)(bytes)) : "memory")
#define MBARRIER_WAIT_PARITY(mbar_smem_addr, phase_parity) do { \
    uint32_t _mbar = (uint32_t)(mbar_smem_addr); \
    uint32_t _parity = (uint32_t)(phase_parity); \
    uint32_t _done; \
    asm volatile( \
        "{\n\t.reg .pred p;\n\t" \
        "mbarrier.try_wait.parity.acquire.cta.shared::cta.b64 p, [%1], %2;\n\t" \
        "selp.b32 %0, 1, 0, p;\n\t}" \
        : "=r"(_done) : "r"(_mbar), "r"(_parity) : "memory"); \
    if (!_done) { \
        asm volatile( \
            "{\n\t.reg .pred P1;\n\t" \
            "WAIT_LOOP_%=:\n\t" \
            "mbarrier.try_wait.parity.acquire.cta.shared::cta.b64 P1, [%0], %1, 0x989680;\n\t" \
            "@P1 bra.uni WAIT_DONE_%=;\n\t" \
            "bra.uni WAIT_LOOP_%=;\n\t" \
            "WAIT_DONE_%=:\n\t}" \
            :: "r"(_mbar), "r"(_parity) : "memory"); \
    } \
} while (0)

__device__ __forceinline__ void ldsm_x4(uint32_t (&r)[4], uint32_t addr) {
    asm volatile("ldmatrix.sync.aligned.m8n8.x4.shared.b16 {%0,%1,%2,%3}, [%4];"
                 : "=r"(r[0]), "=r"(r[1]), "=r"(r[2]), "=r"(r[3]) : "r"(addr));
}
__device__ __forceinline__ void mma16832(float (&c)[4], const uint32_t (&a)[4],
                                         uint32_t b0, uint32_t b1) {
    asm volatile(
        "mma.sync.aligned.m16n8k32.row.col.f32.e4m3.e4m3.f32 "
        "{%0,%1,%2,%3}, {%4,%5,%6,%7}, {%8,%9}, {%0,%1,%2,%3};"
        : "+f"(c[0]), "+f"(c[1]), "+f"(c[2]), "+f"(c[3])
        : "r"(a[0]), "r"(a[1]), "r"(a[2]), "r"(a[3]), "r"(b0), "r"(b1));
}

// ============================ small kernels ================================
__global__ void zero_kernel() {
    int i = blockIdx.x * blockDim.x + threadIdx.x;
    if (i < 4096) g_S[i] = 0.0f;
    if (i < 3 * DDIM) ((double*)g_cs)[i] = 0.0;
    if (i == 0) g_sum_loss = 0.0;
}

// one block per row; 128 threads; writes tiled fp8 + inverse norm
__global__ void __launch_bounds__(128) normalize_kernel(const float* __restrict__ in,
                                                        int which) {
    int row = blockIdx.x;
    uint32_t* outq = (which == 0) ? g_Anq : (which == 1) ? g_Pnq : g_Nnq;
    float*    ginv = (which == 0) ? g_invA : (which == 1) ? g_invP : g_invN;

    int t = threadIdx.x;
    float4 v = ((const float4*)in)[(size_t)row * (DDIM / 4) + t];
    float ss = v.x * v.x + v.y * v.y + v.z * v.z + v.w * v.w;
    #pragma unroll
    for (int off = 16; off; off >>= 1)
        ss += __shfl_xor_sync(0xffffffffu, ss, off);
    __shared__ float wsum[4];
    int warp = t >> 5;
    if ((t & 31) == 0) wsum[warp] = ss;
    __syncthreads();
    float tot = wsum[0] + wsum[1] + wsum[2] + wsum[3];
    float inv = 1.0f / fmaxf(sqrtf(tot), 1e-12f);
    if (t == 0) ginv[row] = inv;

    float sc = inv * FP8_SCALE;
    __nv_fp8x2_storage_t lo = __nv_cvt_float2_to_fp8x2(
        make_float2(v.x * sc, v.y * sc), __NV_SATFINITE, __NV_E4M3);
    __nv_fp8x2_storage_t hi = __nv_cvt_float2_to_fp8x2(
        make_float2(v.z * sc, v.w * sc), __NV_SATFINITE, __NV_E4M3);
    uint32_t packed = (uint32_t)lo | ((uint32_t)hi << 16);

    uint32_t r = (uint32_t)row & 127;
    uint32_t panel = (uint32_t)row >> 7;
    uint32_t kt = (uint32_t)t >> 4;
    uint32_t cc = ((uint32_t)t >> 2) & 3;
    uint32_t w = (uint32_t)t & 3;
    uint32_t sw = cc ^ ((r >> 1) & 3);
    outq[(size_t)panel * 16384 + kt * 2048 + r * 16 + sw * 4 + w] = packed;
}

// exact colsums of normalized rows, computed from raw input * invnorm
__global__ void __launch_bounds__(512) colsum_kernel(const float* __restrict__ in,
                                                     int m, int rows) {
    const float* ginv = (m == 0) ? g_invA : (m == 1) ? g_invP : g_invN;
    int base = blockIdx.x * 256;
    int col = threadIdx.x;
    float acc = 0.0f;
    int lim = min(256, rows - base);
    for (int r = 0; r < lim; r++)
        acc += in[(size_t)(base + r) * DDIM + col] * ginv[base + r];
    atomicAdd(&g_cs[m][col], (double)acc);
}

// ============================ FP8 MMA GEMM =================================
// CTA: 128 threads (4 warps, 2Mx2N), tile 128x128, BK=64B, 8 k-tiles.
// 4-slot cp.async.bulk ring (dynamic smem 64KB), mbarrier per slot.
#define STAGE_BYTES 16384
#define SLOTS 4

template <int MODE>
__global__ void __launch_bounds__(128, 2) mma_kernel() {
    extern __shared__ __align__(128) char sbuf[];
    __shared__ __align__(8) uint64_t mbars[SLOTS];
    const uint32_t sb = smem_to_u32(sbuf);
    const uint32_t mb = smem_to_u32(mbars);

    const int tid = threadIdx.x;
    const int lane = tid & 31;
    const int warp = tid >> 5;
    const int m0 = (warp >> 1) * 64;
    const int n0 = (warp & 1) * 64;
    const int rowBase = blockIdx.y * 128;
    const int colBase = blockIdx.x * 128;

    const char* gA = (const char*)g_Anq + (size_t)(rowBase >> 7) * 65536;
    const char* gB = (const char*)((MODE == 0) ? g_Nnq : g_Pnq)
                     + (size_t)(colBase >> 7) * 65536;

    float c[4][8][4];
    #pragma unroll
    for (int i = 0; i < 4; i++)
        #pragma unroll
        for (int j = 0; j < 8; j++)
            #pragma unroll
            for (int e = 0; e < 4; e++) c[i][j][e] = 0.0f;

    if (tid == 0) {
        #pragma unroll
        for (int s = 0; s < SLOTS; s++) MBARRIER_INIT(mb + s * 8, 1);
    }
    __syncthreads();

    if (tid == 0) {
        #pragma unroll
        for (int s = 0; s < SLOTS; s++) {
            MBARRIER_EXPECT_TX(mb + s * 8, STAGE_BYTES);
            bulk_cp(sb + s * STAGE_BYTES,        gA + (size_t)s * 8192, 8192, mb + s * 8);
            bulk_cp(sb + s * STAGE_BYTES + 8192, gB + (size_t)s * 8192, 8192, mb + s * 8);
        }
    }

    auto load_frags = [&](int slot, int ks, uint32_t (&a)[4][4], uint32_t (&b)[4][4]) {
        uint32_t aB = sb + slot * STAGE_BYTES;
        uint32_t bB = aB + 8192;
        #pragma unroll
        for (int mf = 0; mf < 4; mf++) {
            uint32_t r = m0 + mf * 16 + (lane & 15);
            uint32_t cc = ks * 2 + (lane >> 4);
            uint32_t idx = r * 4 + (cc ^ ((r >> 1) & 3));
            ldsm_x4(a[mf], aB + idx * 16);
        }
        #pragma unroll
        for (int np = 0; np < 4; np++) {
            uint32_t grp = lane >> 3;
            uint32_t n = n0 + np * 16 + ((grp >> 1) ? 8 : 0) + (lane & 7);
            uint32_t cc = ks * 2 + (grp & 1);
            uint32_t idx = n * 4 + (cc ^ ((n >> 1) & 3));
            ldsm_x4(b[np], bB + idx * 16);
        }
    };
    auto mma_all = [&](const uint32_t (&a)[4][4], const uint32_t (&b)[4][4]) {
        #pragma unroll
        for (int mf = 0; mf < 4; mf++)
            #pragma unroll
            for (int nf = 0; nf < 8; nf++)
                mma16832(c[mf][nf], a[mf],
                         b[nf >> 1][(nf & 1) * 2], b[nf >> 1][(nf & 1) * 2 + 1]);
    };

    uint32_t a2[2][4][4], b2[2][4][4];

    for (int kt = 0; kt < 8; kt++) {
        int slot = kt & (SLOTS - 1);
        MBARRIER_WAIT_PARITY(mb + slot * 8, (kt >> 2) & 1);

        load_frags(slot, 0, a2[0], b2[0]);
        load_frags(slot, 1, a2[1], b2[1]);
        mma_all(a2[0], b2[0]);
        mma_all(a2[1], b2[1]);

        __syncthreads();
        if (tid == 0 && kt + SLOTS < 8) {
            int nt = kt + SLOTS;
            MBARRIER_EXPECT_TX(mb + slot * 8, STAGE_BYTES);
            bulk_cp(sb + slot * STAGE_BYTES,        gA + (size_t)nt * 8192, 8192, mb + slot * 8);
            bulk_cp(sb + slot * STAGE_BYTES + 8192, gB + (size_t)nt * 8192, 8192, mb + slot * 8);
        }
    }

    // ---- fused epilogue (accumulator = SCALE^2 * dot) ----
    const float invT = 1.0f / (0.07f * FP8_SCALE * FP8_SCALE);
    const int gID = lane >> 2;

    if (MODE == 0) {
        #pragma unroll
        for (int mf = 0; mf < 4; mf++) {
            float rs0 = 0.0f, rs1 = 0.0f;
            #pragma unroll
            for (int nf = 0; nf < 8; nf++) {
                rs0 += __expf(c[mf][nf][0] * invT) + __expf(c[mf][nf][1] * invT);
                rs1 += __expf(c[mf][nf][2] * invT) + __expf(c[mf][nf][3] * invT);
            }
            rs0 += __shfl_xor_sync(0xffffffffu, rs0, 1);
            rs0 += __shfl_xor_sync(0xffffffffu, rs0, 2);
            rs1 += __shfl_xor_sync(0xffffffffu, rs1, 1);
            rs1 += __shfl_xor_sync(0xffffffffu, rs1, 2);
            if ((lane & 3) == 0) {
                int row = rowBase + m0 + mf * 16 + gID;
                atomicAdd(&g_S[row], rs0);
                atomicAdd(&g_S[row + 8], rs1);
            }
        }
    } else {
        // loss_ij ≈ log S_i + pe/S_i - sim_ij - 1e-8*(1 + S_i/pe)
        // This kernel accumulates only: sum_ij [ pe/S_i - 1e-8*S_i*exp(-t) ]
        // (log S_i, -sim and -1e-8*BP terms are added in finalize)
        float lsum = 0.0f;
        #pragma unroll
        for (int mf = 0; mf < 4; mf++) {
            int row = rowBase + m0 + mf * 16 + gID;
            float S0 = g_S[row];
            float S1 = g_S[row + 8];
            float iS0 = __fdividef(1.0f, S0), cS0 = 1e-8f * S0;
            float iS1 = __fdividef(1.0f, S1), cS1 = 1e-8f * S1;
            #pragma unroll
            for (int nf = 0; nf < 8; nf++) {
                float t0 = c[mf][nf][0] * invT;
                float t1 = c[mf][nf][1] * invT;
                float t2 = c[mf][nf][2] * invT;
                float t3 = c[mf][nf][3] * invT;
                lsum += __expf(t0) * iS0 - cS0 * __expf(-t0);
                lsum += __expf(t1) * iS0 - cS0 * __expf(-t1);
                lsum += __expf(t2) * iS1 - cS1 * __expf(-t2);
                lsum += __expf(t3) * iS1 - cS1 * __expf(-t3);
            }
        }
        double acc = (double)lsum;
        #pragma unroll
        for (int off = 16; off; off >>= 1)
            acc += __shfl_xor_sync(0xffffffffu, acc, off);
        __shared__ double red[4];
        if (lane == 0) red[warp] = acc;
        __syncthreads();
        if (tid == 0)
            atomicAdd(&g_sum_loss, red[0] + red[1] + red[2] + red[3]);
    }
}

// ============================ finalize =====================================
__global__ void __launch_bounds__(512) finalize_kernel(float* __restrict__ out,
                                                       int B, int P, int N) {
    int t = threadIdx.x;
    double logS = 0.0;
    for (int r = t; r < B; r += 512)
        logS += log((double)g_S[r]);
    double dAP = g_cs[0][t] * g_cs[1][t];
    double dAN = g_cs[0][t] * g_cs[2][t];

    // block reduce 3 doubles
    #pragma unroll
    for (int off = 16; off; off >>= 1) {
        logS += __shfl_xor_sync(0xffffffffu, logS, off);
        dAP  += __shfl_xor_sync(0xffffffffu, dAP,  off);
        dAN  += __shfl_xor_sync(0xffffffffu, dAN,  off);
    }
    __shared__ double rA[16], rB[16], rC[16];
    int warp = t >> 5;
    if ((t & 31) == 0) { rA[warp] = logS; rB[warp] = dAP; rC[warp] = dAN; }
    __syncthreads();
    if (t == 0) {
        double sLog = 0.0, sAP = 0.0, sAN = 0.0;
        #pragma unroll
        for (int w = 0; w < 16; w++) { sLog += rA[w]; sAP += rB[w]; sAN += rC[w]; }
        const double T = 0.07;
        double bp = (double)B * (double)P;
        double bn = (double)B * (double)N;
        double mp = sAP / (bp * T);
        double mn = sAN / (bn * T);
        double total = g_sum_loss + (double)P * sLog - sAP / T - 1e-8 * bp;
        out[0] = (float)(total / bp);
        out[1] = (float)mp;
        out[2] = (float)mn;
        out[3] = (float)(mp - mn);
    }
}

// ============================ launch =======================================
extern "C" void kernel_launch(void* const* d_in, const int* in_sizes, int n_in,
                              void* d_out, int out_size) {
    const float* a = (const float*)d_in[0];
    const float* p = (const float*)d_in[1];
    const float* n = (const float*)d_in[2];
    int B = in_sizes[0] / DDIM;   // 4096
    int P = in_sizes[1] / DDIM;   // 4096
    int N = in_sizes[2] / DDIM;   // 16384

    const int SMEM_REQ = SLOTS * STAGE_BYTES;   // 64KB dynamic
    static bool attr_done = false;
    if (!attr_done) {
        cudaFuncSetAttribute(mma_kernel<0>,
            cudaFuncAttributeMaxDynamicSharedMemorySize, SMEM_REQ);
        cudaFuncSetAttribute(mma_kernel<1>,
            cudaFuncAttributeMaxDynamicSharedMemorySize, SMEM_REQ);
        attr_done = true;
    }

    zero_kernel<<<16, 256>>>();
    normalize_kernel<<<B, 128>>>(a, 0);
    normalize_kernel<<<P, 128>>>(p, 1);
    normalize_kernel<<<N, 128>>>(n, 2);

    colsum_kernel<<<B / 256, 512>>>(a, 0, B);
    colsum_kernel<<<P / 256, 512>>>(p, 1, P);
    colsum_kernel<<<N / 256, 512>>>(n, 2, N);

    dim3 gridNeg(N / 128, B / 128);     // 128 x 32
    mma_kernel<0><<<gridNeg, 128, SMEM_REQ>>>();

    dim3 gridPos(P / 128, B / 128);     // 32 x 32
    mma_kernel<1><<<gridPos, 128, SMEM_REQ>>>();

    finalize_kernel<<<1, 512>>>((float*)d_out, B, P, N);
}

// round 8
// speedup vs baseline: 1.1274x; 1.1274x over previous
#include <cuda_runtime.h>
#include <cuda_bf16.h>
#include <cuda_fp8.h>
#include <stdint.h>

// ---------------------------------------------------------------------------
// InfoNCELoss on GB300 (sm_103 legacy mma.sync path, FP8 e4m3 m16n8k32)
// R8 = R6 mma mainloop (3-slot static bulk ring, exp/log epilogue; measured
//      313us) + R7 small-kernel trim (no f32 copies; colsum from raw*invnorm).
// ---------------------------------------------------------------------------

#define DDIM 512
#define FP8_SCALE 32.0f

// fp8 matrices, TILED layout: [panel(128r)][kt(8)][r(128)][64B], swizzled chunks
__device__ __align__(1024) uint32_t g_Anq[(size_t)4096  * 128];
__device__ __align__(1024) uint32_t g_Pnq[(size_t)4096  * 128];
__device__ __align__(1024) uint32_t g_Nnq[(size_t)16384 * 128];
__device__ float    g_invA[4096];
__device__ float    g_invP[4096];
__device__ float    g_invN[16384];
__device__ float    g_S[4096];
__device__ double   g_sum_loss;
__device__ double   g_cs[3][DDIM];

// ============================ PTX helpers ==================================
__device__ __forceinline__ uint32_t smem_to_u32(const void* p) {
    uint32_t a;
    asm("{ .reg .u64 t; cvta.to.shared.u64 t, %1; cvt.u32.u64 %0, t; }"
        : "=r"(a) : "l"(p));
    return a;
}
__device__ __forceinline__ void bulk_cp(uint32_t dst, const void* src,
                                        uint32_t bytes, uint32_t mbar) {
    asm volatile(
        "cp.async.bulk.shared::cta.global.mbarrier::complete_tx::bytes "
        "[%0], [%1], %2, [%3];"
        :: "r"(dst), "l"(src), "r"(bytes), "r"(mbar) : "memory");
}
#define MBARRIER_INIT(mbar, count) \
    asm volatile("mbarrier.init.shared.b64 [%0], %1;" \
        :: "r"((uint32_t)(mbar)), "r"((uint32_t)(count)) : "memory")
#define MBARRIER_EXPECT_TX(mbar, bytes) \
    asm volatile("mbarrier.arrive.expect_tx.shared.b64 _, [%0], %1;" \
        :: "r"((uint32_t)(mbar)), "r"((uint32_t)(bytes)) : "memory")
#define MBARRIER_WAIT_PARITY(mbar_smem_addr, phase_parity) do { \
    uint32_t _mbar = (uint32_t)(mbar_smem_addr); \
    uint32_t _parity = (uint32_t)(phase_parity); \
    uint32_t _done; \
    asm volatile( \
        "{\n\t.reg .pred p;\n\t" \
        "mbarrier.try_wait.parity.acquire.cta.shared::cta.b64 p, [%1], %2;\n\t" \
        "selp.b32 %0, 1, 0, p;\n\t}" \
        : "=r"(_done) : "r"(_mbar), "r"(_parity) : "memory"); \
    if (!_done) { \
        asm volatile( \
            "{\n\t.reg .pred P1;\n\t" \
            "WAIT_LOOP_%=:\n\t" \
            "mbarrier.try_wait.parity.acquire.cta.shared::cta.b64 P1, [%0], %1, 0x989680;\n\t" \
            "@P1 bra.uni WAIT_DONE_%=;\n\t" \
            "bra.uni WAIT_LOOP_%=;\n\t" \
            "WAIT_DONE_%=:\n\t}" \
            :: "r"(_mbar), "r"(_parity) : "memory"); \
    } \
} while (0)

__device__ __forceinline__ void ldsm_x4(uint32_t (&r)[4], uint32_t addr) {
    asm volatile("ldmatrix.sync.aligned.m8n8.x4.shared.b16 {%0,%1,%2,%3}, [%4];"
                 : "=r"(r[0]), "=r"(r[1]), "=r"(r[2]), "=r"(r[3]) : "r"(addr));
}
__device__ __forceinline__ void mma16832(float (&c)[4], const uint32_t (&a)[4],
                                         uint32_t b0, uint32_t b1) {
    asm volatile(
        "mma.sync.aligned.m16n8k32.row.col.f32.e4m3.e4m3.f32 "
        "{%0,%1,%2,%3}, {%4,%5,%6,%7}, {%8,%9}, {%0,%1,%2,%3};"
        : "+f"(c[0]), "+f"(c[1]), "+f"(c[2]), "+f"(c[3])
        : "r"(a[0]), "r"(a[1]), "r"(a[2]), "r"(a[3]), "r"(b0), "r"(b1));
}

// ============================ small kernels ================================
__global__ void zero_kernel() {
    int i = blockIdx.x * blockDim.x + threadIdx.x;
    if (i < 4096) g_S[i] = 0.0f;
    if (i < 3 * DDIM) ((double*)g_cs)[i] = 0.0;
    if (i == 0) g_sum_loss = 0.0;
}

// one block per row; 128 threads; writes tiled fp8 + inverse norm
__global__ void __launch_bounds__(128) normalize_kernel(const float* __restrict__ in,
                                                        int which) {
    int row = blockIdx.x;
    uint32_t* outq = (which == 0) ? g_Anq : (which == 1) ? g_Pnq : g_Nnq;
    float*    ginv = (which == 0) ? g_invA : (which == 1) ? g_invP : g_invN;

    int t = threadIdx.x;
    float4 v = ((const float4*)in)[(size_t)row * (DDIM / 4) + t];
    float ss = v.x * v.x + v.y * v.y + v.z * v.z + v.w * v.w;
    #pragma unroll
    for (int off = 16; off; off >>= 1)
        ss += __shfl_xor_sync(0xffffffffu, ss, off);
    __shared__ float wsum[4];
    int warp = t >> 5;
    if ((t & 31) == 0) wsum[warp] = ss;
    __syncthreads();
    float tot = wsum[0] + wsum[1] + wsum[2] + wsum[3];
    float inv = 1.0f / fmaxf(sqrtf(tot), 1e-12f);
    if (t == 0) ginv[row] = inv;

    float sc = inv * FP8_SCALE;
    __nv_fp8x2_storage_t lo = __nv_cvt_float2_to_fp8x2(
        make_float2(v.x * sc, v.y * sc), __NV_SATFINITE, __NV_E4M3);
    __nv_fp8x2_storage_t hi = __nv_cvt_float2_to_fp8x2(
        make_float2(v.z * sc, v.w * sc), __NV_SATFINITE, __NV_E4M3);
    uint32_t packed = (uint32_t)lo | ((uint32_t)hi << 16);

    uint32_t r = (uint32_t)row & 127;
    uint32_t panel = (uint32_t)row >> 7;
    uint32_t kt = (uint32_t)t >> 4;
    uint32_t cc = ((uint32_t)t >> 2) & 3;
    uint32_t w = (uint32_t)t & 3;
    uint32_t sw = cc ^ ((r >> 1) & 3);
    outq[(size_t)panel * 16384 + kt * 2048 + r * 16 + sw * 4 + w] = packed;
}

// exact colsums of normalized rows, from raw input * invnorm
__global__ void __launch_bounds__(512) colsum_kernel(const float* __restrict__ in,
                                                     int m, int rows) {
    const float* ginv = (m == 0) ? g_invA : (m == 1) ? g_invP : g_invN;
    int base = blockIdx.x * 256;
    int col = threadIdx.x;
    float acc = 0.0f;
    int lim = min(256, rows - base);
    for (int r = 0; r < lim; r++)
        acc += in[(size_t)(base + r) * DDIM + col] * ginv[base + r];
    atomicAdd(&g_cs[m][col], (double)acc);
}

// ============================ FP8 MMA GEMM =================================
// CTA: 128 threads (4 warps, 2Mx2N), tile 128x128, BK=64B, 8 k-tiles.
// 3-slot cp.async.bulk ring (STATIC 48KB smem), mbarrier per slot.  [R6 config]
#define STAGE_BYTES 16384

template <int MODE>
__global__ void __launch_bounds__(128, 2) mma_kernel() {
    __shared__ __align__(128) char sbuf[3 * STAGE_BYTES];   // 48KB
    __shared__ __align__(8) uint64_t mbars[3];
    const uint32_t sb = smem_to_u32(sbuf);
    const uint32_t mb = smem_to_u32(mbars);

    const int tid = threadIdx.x;
    const int lane = tid & 31;
    const int warp = tid >> 5;
    const int m0 = (warp >> 1) * 64;
    const int n0 = (warp & 1) * 64;
    const int rowBase = blockIdx.y * 128;
    const int colBase = blockIdx.x * 128;

    const char* gA = (const char*)g_Anq + (size_t)(rowBase >> 7) * 65536;
    const char* gB = (const char*)((MODE == 0) ? g_Nnq : g_Pnq)
                     + (size_t)(colBase >> 7) * 65536;

    float c[4][8][4];
    #pragma unroll
    for (int i = 0; i < 4; i++)
        #pragma unroll
        for (int j = 0; j < 8; j++)
            #pragma unroll
            for (int e = 0; e < 4; e++) c[i][j][e] = 0.0f;

    if (tid == 0) {
        #pragma unroll
        for (int s = 0; s < 3; s++) MBARRIER_INIT(mb + s * 8, 1);
    }
    __syncthreads();

    if (tid == 0) {
        #pragma unroll
        for (int s = 0; s < 3; s++) {
            MBARRIER_EXPECT_TX(mb + s * 8, STAGE_BYTES);
            bulk_cp(sb + s * STAGE_BYTES,        gA + (size_t)s * 8192, 8192, mb + s * 8);
            bulk_cp(sb + s * STAGE_BYTES + 8192, gB + (size_t)s * 8192, 8192, mb + s * 8);
        }
    }

    auto load_frags = [&](int slot, int ks, uint32_t (&a)[4][4], uint32_t (&b)[4][4]) {
        uint32_t aB = sb + slot * STAGE_BYTES;
        uint32_t bB = aB + 8192;
        #pragma unroll
        for (int mf = 0; mf < 4; mf++) {
            uint32_t r = m0 + mf * 16 + (lane & 15);
            uint32_t cc = ks * 2 + (lane >> 4);
            uint32_t idx = r * 4 + (cc ^ ((r >> 1) & 3));
            ldsm_x4(a[mf], aB + idx * 16);
        }
        #pragma unroll
        for (int np = 0; np < 4; np++) {
            uint32_t grp = lane >> 3;
            uint32_t n = n0 + np * 16 + ((grp >> 1) ? 8 : 0) + (lane & 7);
            uint32_t cc = ks * 2 + (grp & 1);
            uint32_t idx = n * 4 + (cc ^ ((n >> 1) & 3));
            ldsm_x4(b[np], bB + idx * 16);
        }
    };
    auto mma_all = [&](const uint32_t (&a)[4][4], const uint32_t (&b)[4][4]) {
        #pragma unroll
        for (int mf = 0; mf < 4; mf++)
            #pragma unroll
            for (int nf = 0; nf < 8; nf++)
                mma16832(c[mf][nf], a[mf],
                         b[nf >> 1][(nf & 1) * 2], b[nf >> 1][(nf & 1) * 2 + 1]);
    };

    uint32_t a2[2][4][4], b2[2][4][4];

    for (int kt = 0; kt < 8; kt++) {
        int slot = kt % 3;
        MBARRIER_WAIT_PARITY(mb + slot * 8, (kt / 3) & 1);

        load_frags(slot, 0, a2[0], b2[0]);
        load_frags(slot, 1, a2[1], b2[1]);
        mma_all(a2[0], b2[0]);
        mma_all(a2[1], b2[1]);

        __syncthreads();      // all warps done with this slot
        if (tid == 0 && kt + 3 < 8) {
            int nt = kt + 3;
            MBARRIER_EXPECT_TX(mb + slot * 8, STAGE_BYTES);
            bulk_cp(sb + slot * STAGE_BYTES,        gA + (size_t)nt * 8192, 8192, mb + slot * 8);
            bulk_cp(sb + slot * STAGE_BYTES + 8192, gB + (size_t)nt * 8192, 8192, mb + slot * 8);
        }
    }

    // ---- fused epilogue (accumulator = SCALE^2 * dot) ----
    const float invT = 1.0f / (0.07f * FP8_SCALE * FP8_SCALE);
    const int gID = lane >> 2;

    if (MODE == 0) {
        #pragma unroll
        for (int mf = 0; mf < 4; mf++) {
            float rs0 = 0.0f, rs1 = 0.0f;
            #pragma unroll
            for (int nf = 0; nf < 8; nf++) {
                rs0 += __expf(c[mf][nf][0] * invT) + __expf(c[mf][nf][1] * invT);
                rs1 += __expf(c[mf][nf][2] * invT) + __expf(c[mf][nf][3] * invT);
            }
            rs0 += __shfl_xor_sync(0xffffffffu, rs0, 1);
            rs0 += __shfl_xor_sync(0xffffffffu, rs0, 2);
            rs1 += __shfl_xor_sync(0xffffffffu, rs1, 1);
            rs1 += __shfl_xor_sync(0xffffffffu, rs1, 2);
            if ((lane & 3) == 0) {
                int row = rowBase + m0 + mf * 16 + gID;
                atomicAdd(&g_S[row], rs0);
                atomicAdd(&g_S[row + 8], rs1);
            }
        }
    } else {
        float lsum = 0.0f;
        #pragma unroll
        for (int mf = 0; mf < 4; mf++) {
            int row = rowBase + m0 + mf * 16 + gID;
            float S0 = g_S[row];
            float S1 = g_S[row + 8];
            #pragma unroll
            for (int nf = 0; nf < 8; nf++) {
                float p0 = __expf(c[mf][nf][0] * invT);
                float p1 = __expf(c[mf][nf][1] * invT);
                float p2 = __expf(c[mf][nf][2] * invT);
                float p3 = __expf(c[mf][nf][3] * invT);
                lsum += __logf(__fdividef(p0, p0 + S0) + 1e-8f);
                lsum += __logf(__fdividef(p1, p1 + S0) + 1e-8f);
                lsum += __logf(__fdividef(p2, p2 + S1) + 1e-8f);
                lsum += __logf(__fdividef(p3, p3 + S1) + 1e-8f);
            }
        }
        double acc = -(double)lsum;
        #pragma unroll
        for (int off = 16; off; off >>= 1)
            acc += __shfl_xor_sync(0xffffffffu, acc, off);
        __shared__ double red[4];
        if (lane == 0) red[warp] = acc;
        __syncthreads();
        if (tid == 0)
            atomicAdd(&g_sum_loss, red[0] + red[1] + red[2] + red[3]);
    }
}

// ============================ finalize =====================================
__global__ void __launch_bounds__(512) finalize_kernel(float* __restrict__ out,
                                                       int B, int P, int N) {
    int t = threadIdx.x;
    double dAP = g_cs[0][t] * g_cs[1][t];
    double dAN = g_cs[0][t] * g_cs[2][t];
    #pragma unroll
    for (int off = 16; off; off >>= 1) {
        dAP += __shfl_xor_sync(0xffffffffu, dAP, off);
        dAN += __shfl_xor_sync(0xffffffffu, dAN, off);
    }
    __shared__ double rB[16], rC[16];
    int warp = t >> 5;
    if ((t & 31) == 0) { rB[warp] = dAP; rC[warp] = dAN; }
    __syncthreads();
    if (t == 0) {
        double sAP = 0.0, sAN = 0.0;
        #pragma unroll
        for (int w = 0; w < 16; w++) { sAP += rB[w]; sAN += rC[w]; }
        const double T = 0.07;
        double bp = (double)B * (double)P;
        double bn = (double)B * (double)N;
        double mp = sAP / (bp * T);
        double mn = sAN / (bn * T);
        double tl = g_sum_loss / bp;
        out[0] = (float)tl;
        out[1] = (float)mp;
        out[2] = (float)mn;
        out[3] = (float)(mp - mn);
    }
}

// ============================ launch =======================================
extern "C" void kernel_launch(void* const* d_in, const int* in_sizes, int n_in,
                              void* d_out, int out_size) {
    const float* a = (const float*)d_in[0];
    const float* p = (const float*)d_in[1];
    const float* n = (const float*)d_in[2];
    int B = in_sizes[0] / DDIM;   // 4096
    int P = in_sizes[1] / DDIM;   // 4096
    int N = in_sizes[2] / DDIM;   // 16384

    zero_kernel<<<16, 256>>>();
    normalize_kernel<<<B, 128>>>(a, 0);
    normalize_kernel<<<P, 128>>>(p, 1);
    normalize_kernel<<<N, 128>>>(n, 2);

    colsum_kernel<<<B / 256, 512>>>(a, 0, B);
    colsum_kernel<<<P / 256, 512>>>(p, 1, P);
    colsum_kernel<<<N / 256, 512>>>(n, 2, N);

    dim3 gridNeg(N / 128, B / 128);     // 128 x 32
    mma_kernel<0><<<gridNeg, 128>>>();

    dim3 gridPos(P / 128, B / 128);     // 32 x 32
    mma_kernel<1><<<gridPos, 128>>>();

    finalize_kernel<<<1, 512>>>((float*)d_out, B, P, N);
}